// round 16
// baseline (speedup 1.0000x reference)
#include <cuda_runtime.h>
#include <cuda_fp16.h>
#include <cstdint>
#include <math.h>

// NTXentLoss: fp16 HMMA (fp16 accumulators), upper-triangular 128x128 tiles,
// 2-stage cp.async ring, 3 CTAs/SM. Raw-z fp16 storage; per-row inv-norm
// applied in the GEMM epilogue (removes reduce->store dependency in
// normalize). 2N=8192, D=512.

#define TWO_N   8192
#define NHALF   4096
#define DDIM    512
#define INV_T   14.285714285714286f
#define LOG2E   1.4426950408889634f
#define LN2F    0.6931471805599453f
#define EXP_SCALE (INV_T * LOG2E)

#define BM 128
#define BN 128
#define NCHUNK 8                     // K chunks of 64 fp16 (128B)
#define TILE_B (BM * 128)            // 16KB per operand chunk
#define NSTAGE 2
#define SMEM_BYTES (2 * NSTAGE * TILE_B)   // 64KB

#define NTILE 64
#define NUPPER 2080

__device__ static __half g_zh[TWO_N * DDIM];     // raw z in fp16
__device__ static float g_inv[TWO_N];            // 1/||z|| per row
__device__ static float g_rowsum[TWO_N];
__device__ static float g_pos[TWO_N];

__device__ __forceinline__ uint32_t smem_u32(const void* p) {
    uint32_t a;
    asm("{ .reg .u64 t; cvta.to.shared.u64 t, %1; cvt.u32.u64 %0, t; }"
        : "=r"(a) : "l"(p));
    return a;
}
#define CP16(dst, src) \
    asm volatile("cp.async.cg.shared.global [%0], [%1], 16;" :: "r"(dst), "l"(src))
#define CPCOMMIT() asm volatile("cp.async.commit_group;" ::: "memory")

#define LDSM4(r0, r1, r2, r3, addr)                                         \
    asm volatile("ldmatrix.sync.aligned.m8n8.x4.shared.b16 {%0,%1,%2,%3}, [%4];" \
        : "=r"(r0), "=r"(r1), "=r"(r2), "=r"(r3) : "r"(addr))

#define MMAH(c, a, b0, b1)                                                  \
    asm volatile("mma.sync.aligned.m16n8k16.row.col.f16.f16.f16.f16 "       \
        "{%0,%1}, {%2,%3,%4,%5}, {%6,%7}, {%0,%1};"                         \
        : "+r"((c)[0]), "+r"((c)[1])                                        \
        : "r"((a)[0]), "r"((a)[1]), "r"((a)[2]), "r"((a)[3]),               \
          "r"(b0), "r"(b1))

__device__ __forceinline__ float ex2_approx(float x) {
    float r;
    asm("ex2.approx.ftz.f32 %0, %1;" : "=f"(r) : "f"(x));
    return r;
}
__device__ __forceinline__ float lg2_approx(float x) {
    float r;
    asm("lg2.approx.ftz.f32 %0, %1;" : "=f"(r) : "f"(x));
    return r;
}

// ---------------------------------------------------------------------------
// Kernel 1: warp per row: store raw fp16 z immediately (no dependency on the
// reduction), compute 1/||z|| in parallel, zero rowsum.
// ---------------------------------------------------------------------------
__global__ void k_normalize(const float* __restrict__ z1,
                            const float* __restrict__ z2) {
    const int row  = (blockIdx.x * blockDim.x + threadIdx.x) >> 5;
    const int lane = threadIdx.x & 31;
    const float* src = (row < NHALF) ? (z1 + (size_t)row * DDIM)
                                     : (z2 + (size_t)(row - NHALF) * DDIM);
    const float4* src4 = (const float4*)src;
    __half2* dst = (__half2*)(g_zh + (size_t)row * DDIM);

    float4 v[4];
    #pragma unroll
    for (int i = 0; i < 4; i++)
        v[i] = __ldcs(src4 + lane + 32 * i);

    // stores depend only on the loads — issue right away
    float ss = 0.0f;
    #pragma unroll
    for (int i = 0; i < 4; i++) {
        dst[(lane + 32 * i) * 2]     = __floats2half2_rn(v[i].x, v[i].y);
        dst[(lane + 32 * i) * 2 + 1] = __floats2half2_rn(v[i].z, v[i].w);
        ss += v[i].x * v[i].x + v[i].y * v[i].y + v[i].z * v[i].z + v[i].w * v[i].w;
    }
    #pragma unroll
    for (int off = 16; off > 0; off >>= 1)
        ss += __shfl_xor_sync(0xffffffffu, ss, off);
    if (lane == 0) {
        g_inv[row]    = rsqrtf(fmaxf(ss, 1e-16f));   // ||z||>=eps for this data
        g_rowsum[row] = 0.0f;
    }
}

// ---------------------------------------------------------------------------
// Kernel 2: 128x128 tiles, 8 warps (2x4), warp tile 64x32, 2-stage ring.
// Epilogue rescales dots by inv_i*inv_j (smem-cached per-row scales).
// ---------------------------------------------------------------------------
__device__ __forceinline__ void load_chunk(uint32_t base, const char* gsrc,
                                           int c, int tid) {
    #pragma unroll
    for (int i = 0; i < 4; i++) {
        int idx = tid + i * 256;        // 0..1023
        int r = idx >> 3, s = idx & 7;
        uint32_t off = (uint32_t)(r * 128 + ((s ^ (r & 7)) * 16));
        CP16(base + off, gsrc + (size_t)r * 1024 + (size_t)c * 128 + s * 16);
    }
}

__global__ void __launch_bounds__(256, 3) k_sim() {
    const int t = blockIdx.x;
    int by = (int)(64.5f - sqrtf(64.5f * 64.5f - 2.0f * (float)t));
    while ((by + 1) * NTILE - ((by + 1) * by) / 2 <= t) by++;
    while (by * NTILE - (by * (by - 1)) / 2 > t) by--;
    const int bx = by + (t - (by * NTILE - (by * (by - 1)) / 2));

    extern __shared__ char smraw[];
    uint32_t sA[NSTAGE], sB[NSTAGE];
    #pragma unroll
    for (int i = 0; i < NSTAGE; i++) {
        sA[i] = smem_u32(smraw) + i * TILE_B;
        sB[i] = smem_u32(smraw) + (NSTAGE + i) * TILE_B;
    }

    __shared__ float rowsum_s[BM];
    __shared__ float colsum_s[BN];
    __shared__ float srow_s[BM];
    __shared__ float scol_s[BN];

    const int tid  = threadIdx.x;
    const int wid  = tid >> 5;
    const int lane = tid & 31;
    const int wm = wid & 1;
    const int wn = wid >> 1;

    const int rowbase = by * BM;
    const int colbase = bx * BN;
    if (tid < BM) { rowsum_s[tid] = 0.0f; srow_s[tid] = g_inv[rowbase + tid]; }
    if (tid < BN) { colsum_s[tid] = 0.0f; scol_s[tid] = g_inv[colbase + tid]; }

    const char* gA = (const char*)(g_zh + (size_t)rowbase * DDIM);
    const char* gB = (const char*)(g_zh + (size_t)colbase * DDIM);

    uint32_t acc[4][4][2];
    #pragma unroll
    for (int i = 0; i < 4; i++)
        #pragma unroll
        for (int j = 0; j < 4; j++) { acc[i][j][0] = 0u; acc[i][j][1] = 0u; }

    const int lrow = lane & 15;
    const int lseg = lane >> 4;

    load_chunk(sA[0], gA, 0, tid);
    load_chunk(sB[0], gB, 0, tid);
    CPCOMMIT();

    #pragma unroll 1
    for (int c = 0; c < NCHUNK; c++) {
        const int cur = c & 1;
        asm volatile("cp.async.wait_group 0;" ::: "memory");
        __syncthreads();
        if (c + 1 < NCHUNK) {
            load_chunk(sA[cur ^ 1], gA, c + 1, tid);
            load_chunk(sB[cur ^ 1], gB, c + 1, tid);
            CPCOMMIT();
        }

        #pragma unroll
        for (int kk = 0; kk < 4; kk++) {
            const int seg = 2 * kk + lseg;
            uint32_t a[4][4], b[2][4];
            #pragma unroll
            for (int mi = 0; mi < 4; mi++) {
                int r = wm * 64 + mi * 16 + lrow;
                uint32_t addr = sA[cur] + (uint32_t)(r * 128 + ((seg ^ (r & 7)) * 16));
                LDSM4(a[mi][0], a[mi][1], a[mi][2], a[mi][3], addr);
            }
            #pragma unroll
            for (int bt = 0; bt < 2; bt++) {
                int r = wn * 32 + bt * 16 + lrow;
                uint32_t addr = sB[cur] + (uint32_t)(r * 128 + ((seg ^ (r & 7)) * 16));
                LDSM4(b[bt][0], b[bt][1], b[bt][2], b[bt][3], addr);
            }
            #pragma unroll
            for (int mi = 0; mi < 4; mi++)
                #pragma unroll
                for (int bt = 0; bt < 2; bt++) {
                    MMAH(acc[mi][bt * 2 + 0], a[mi], b[bt][0], b[bt][2]);
                    MMAH(acc[mi][bt * 2 + 1], a[mi], b[bt][1], b[bt][3]);
                }
        }
    }

    // ---- epilogue: rescale by inv_i*inv_j, exp, mask, positives, reduce ----
    const int qr = lane >> 2;
    const int qc = (lane & 3) * 2;
    float colp[4][2];
    #pragma unroll
    for (int nt = 0; nt < 4; nt++) { colp[nt][0] = 0.0f; colp[nt][1] = 0.0f; }

    #pragma unroll
    for (int mi = 0; mi < 4; mi++) {
        const int r0 = wm * 64 + mi * 16 + qr;
        const int gi0 = rowbase + r0;
        const int gi1 = gi0 + 8;
        const float si0 = srow_s[r0];
        const float si1 = srow_s[r0 + 8];
        float rs0 = 0.0f, rs1 = 0.0f;
        #pragma unroll
        for (int nt = 0; nt < 4; nt++) {
            const int c0 = wn * 32 + nt * 8 + qc;
            const int gj0 = colbase + c0;
            const int gj1 = gj0 + 1;
            const float sj0 = scol_s[c0];
            const float sj1 = scol_s[c0 + 1];
            const float2 lo = __half22float2(*(const __half2*)&acc[mi][nt][0]);
            const float2 hi = __half22float2(*(const __half2*)&acc[mi][nt][1]);
            const float d00 = lo.x * (si0 * sj0), d01 = lo.y * (si0 * sj1);
            const float d10 = hi.x * (si1 * sj0), d11 = hi.y * (si1 * sj1);

            float e00 = ex2_approx(fmaf(d00, EXP_SCALE, -EXP_SCALE));
            float e01 = ex2_approx(fmaf(d01, EXP_SCALE, -EXP_SCALE));
            float e10 = ex2_approx(fmaf(d10, EXP_SCALE, -EXP_SCALE));
            float e11 = ex2_approx(fmaf(d11, EXP_SCALE, -EXP_SCALE));
            if (gj0 <= gi0) e00 = 0.0f;
            if (gj1 <= gi0) e01 = 0.0f;
            if (gj0 <= gi1) e10 = 0.0f;
            if (gj1 <= gi1) e11 = 0.0f;

            if (gj0 == gi0 + NHALF) { float s = d00 * INV_T; g_pos[gi0] = s; g_pos[gj0] = s; }
            if (gj1 == gi0 + NHALF) { float s = d01 * INV_T; g_pos[gi0] = s; g_pos[gj1] = s; }
            if (gj0 == gi1 + NHALF) { float s = d10 * INV_T; g_pos[gi1] = s; g_pos[gj0] = s; }
            if (gj1 == gi1 + NHALF) { float s = d11 * INV_T; g_pos[gi1] = s; g_pos[gj1] = s; }

            rs0 += e00 + e01;
            rs1 += e10 + e11;
            colp[nt][0] += e00 + e10;
            colp[nt][1] += e01 + e11;
        }
        rs0 += __shfl_xor_sync(0xffffffffu, rs0, 1);
        rs0 += __shfl_xor_sync(0xffffffffu, rs0, 2);
        rs1 += __shfl_xor_sync(0xffffffffu, rs1, 1);
        rs1 += __shfl_xor_sync(0xffffffffu, rs1, 2);
        if ((lane & 3) == 0) {
            atomicAdd(&rowsum_s[wm * 64 + mi * 16 + qr], rs0);
            atomicAdd(&rowsum_s[wm * 64 + mi * 16 + qr + 8], rs1);
        }
    }
    #pragma unroll
    for (int nt = 0; nt < 4; nt++) {
        #pragma unroll
        for (int j = 0; j < 2; j++) {
            float v = colp[nt][j];
            v += __shfl_xor_sync(0xffffffffu, v, 4);
            v += __shfl_xor_sync(0xffffffffu, v, 8);
            v += __shfl_xor_sync(0xffffffffu, v, 16);
            if (lane < 4 && (lane & 3) == (qc >> 1))
                atomicAdd(&colsum_s[wn * 32 + nt * 8 + qc + j], v);
        }
    }
    __syncthreads();

    if (tid < BM) atomicAdd(&g_rowsum[rowbase + tid], rowsum_s[tid]);
    if (tid < BN) atomicAdd(&g_rowsum[colbase + tid], colsum_s[tid]);
}

// ---------------------------------------------------------------------------
// Kernel 3: loss mean, single 1024-thread block, vectorized + approx log
// ---------------------------------------------------------------------------
__global__ void k_final(float* __restrict__ out) {
    const int tid = threadIdx.x;    // 1024
    float sum = 0.0f;
    const float4* pos4 = (const float4*)g_pos;
    const float4* row4 = (const float4*)g_rowsum;
    #pragma unroll
    for (int i = 0; i < 2; i++) {
        const int idx = tid + i * 1024;      // 2048 float4 total
        float4 p = pos4[idx];
        float4 r = row4[idx];
        sum += -(p.x + p.y + p.z + p.w) + 4.0f * INV_T
             + (lg2_approx(r.x) + lg2_approx(r.y)
              + lg2_approx(r.z) + lg2_approx(r.w)) * LN2F;
    }
    #pragma unroll
    for (int off = 16; off > 0; off >>= 1)
        sum += __shfl_xor_sync(0xffffffffu, sum, off);
    __shared__ float red[32];
    if ((tid & 31) == 0) red[tid >> 5] = sum;
    __syncthreads();
    if (tid < 32) {
        float v = red[tid];
        #pragma unroll
        for (int off = 16; off > 0; off >>= 1)
            v += __shfl_xor_sync(0xffffffffu, v, off);
        if (tid == 0) out[0] = v / (float)TWO_N;
    }
}

extern "C" void kernel_launch(void* const* d_in, const int* in_sizes, int n_in,
                              void* d_out, int out_size) {
    const float* z1 = (const float*)d_in[0];
    const float* z2 = (const float*)d_in[1];
    float* out = (float*)d_out;

    static int attr_set = 0;
    if (!attr_set) {
        cudaFuncSetAttribute(k_sim, cudaFuncAttributeMaxDynamicSharedMemorySize,
                             SMEM_BYTES);
        attr_set = 1;
    }

    k_normalize<<<TWO_N / 8, 256>>>(z1, z2);
    k_sim<<<NUPPER, 256, SMEM_BYTES>>>();
    k_final<<<1, 1024>>>(out);
}

// round 17
// speedup vs baseline: 1.0288x; 1.0288x over previous
#include <cuda_runtime.h>
#include <cuda_fp16.h>
#include <cstdint>
#include <math.h>

// NTXentLoss: fp16 HMMA (fp16 accumulators), upper-triangular 128x128 tiles,
// 2-stage cp.async ring, 3 CTAs/SM, separate finalization kernel.
// 2N=8192, D=512.  Final configuration: R15 topology (best measured 106.3us)
// with plain (non-streaming) loads in normalize per R8's measurement.

#define TWO_N   8192
#define NHALF   4096
#define DDIM    512
#define INV_T   14.285714285714286f
#define LOG2E   1.4426950408889634f
#define LN2F    0.6931471805599453f
#define EXP_SCALE (INV_T * LOG2E)

#define BM 128
#define BN 128
#define NCHUNK 8                     // K chunks of 64 fp16 (128B)
#define TILE_B (BM * 128)            // 16KB per operand chunk
#define NSTAGE 2
#define SMEM_BYTES (2 * NSTAGE * TILE_B)   // 64KB

#define NTILE 64
#define NUPPER 2080

__device__ static __half g_zn[TWO_N * DDIM];
__device__ static float g_rowsum[TWO_N];
__device__ static float g_pos[TWO_N];

__device__ __forceinline__ uint32_t smem_u32(const void* p) {
    uint32_t a;
    asm("{ .reg .u64 t; cvta.to.shared.u64 t, %1; cvt.u32.u64 %0, t; }"
        : "=r"(a) : "l"(p));
    return a;
}
#define CP16(dst, src) \
    asm volatile("cp.async.cg.shared.global [%0], [%1], 16;" :: "r"(dst), "l"(src))
#define CPCOMMIT() asm volatile("cp.async.commit_group;" ::: "memory")

#define LDSM4(r0, r1, r2, r3, addr)                                         \
    asm volatile("ldmatrix.sync.aligned.m8n8.x4.shared.b16 {%0,%1,%2,%3}, [%4];" \
        : "=r"(r0), "=r"(r1), "=r"(r2), "=r"(r3) : "r"(addr))

#define MMAH(c, a, b0, b1)                                                  \
    asm volatile("mma.sync.aligned.m16n8k16.row.col.f16.f16.f16.f16 "       \
        "{%0,%1}, {%2,%3,%4,%5}, {%6,%7}, {%0,%1};"                         \
        : "+r"((c)[0]), "+r"((c)[1])                                        \
        : "r"((a)[0]), "r"((a)[1]), "r"((a)[2]), "r"((a)[3]),               \
          "r"(b0), "r"(b1))

__device__ __forceinline__ float ex2_approx(float x) {
    float r;
    asm("ex2.approx.ftz.f32 %0, %1;" : "=f"(r) : "f"(x));
    return r;
}
__device__ __forceinline__ float lg2_approx(float x) {
    float r;
    asm("lg2.approx.ftz.f32 %0, %1;" : "=f"(r) : "f"(x));
    return r;
}

// ---------------------------------------------------------------------------
// Kernel 1: warp per row: normalize -> fp16, zero rowsum.
// ---------------------------------------------------------------------------
__global__ void k_normalize(const float* __restrict__ z1,
                            const float* __restrict__ z2) {
    const int row  = (blockIdx.x * blockDim.x + threadIdx.x) >> 5;
    const int lane = threadIdx.x & 31;
    const float* src = (row < NHALF) ? (z1 + (size_t)row * DDIM)
                                     : (z2 + (size_t)(row - NHALF) * DDIM);
    const float4* src4 = (const float4*)src;
    float4 v[4];
    float ss = 0.0f;
    #pragma unroll
    for (int i = 0; i < 4; i++) {
        v[i] = src4[lane + 32 * i];
        ss += v[i].x * v[i].x + v[i].y * v[i].y + v[i].z * v[i].z + v[i].w * v[i].w;
    }
    #pragma unroll
    for (int off = 16; off > 0; off >>= 1)
        ss += __shfl_xor_sync(0xffffffffu, ss, off);
    const float inv = rsqrtf(fmaxf(ss, 1e-16f));   // ||z|| >> eps for this data
    if (lane == 0) g_rowsum[row] = 0.0f;

    __half2* dst = (__half2*)(g_zn + (size_t)row * DDIM);
    #pragma unroll
    for (int i = 0; i < 4; i++) {
        __half2 p0 = __floats2half2_rn(v[i].x * inv, v[i].y * inv);
        __half2 p1 = __floats2half2_rn(v[i].z * inv, v[i].w * inv);
        dst[(lane + 32 * i) * 2]     = p0;
        dst[(lane + 32 * i) * 2 + 1] = p1;
    }
}

// ---------------------------------------------------------------------------
// Kernel 2: 128x128 tiles, 8 warps (2x4), warp tile 64x32, 2-stage ring.
// ---------------------------------------------------------------------------
__device__ __forceinline__ void load_chunk(uint32_t base, const char* gsrc,
                                           int c, int tid) {
    #pragma unroll
    for (int i = 0; i < 4; i++) {
        int idx = tid + i * 256;        // 0..1023
        int r = idx >> 3, s = idx & 7;
        uint32_t off = (uint32_t)(r * 128 + ((s ^ (r & 7)) * 16));
        CP16(base + off, gsrc + (size_t)r * 1024 + (size_t)c * 128 + s * 16);
    }
}

__global__ void __launch_bounds__(256, 3) k_sim() {
    const int t = blockIdx.x;
    int by = (int)(64.5f - sqrtf(64.5f * 64.5f - 2.0f * (float)t));
    while ((by + 1) * NTILE - ((by + 1) * by) / 2 <= t) by++;
    while (by * NTILE - (by * (by - 1)) / 2 > t) by--;
    const int bx = by + (t - (by * NTILE - (by * (by - 1)) / 2));

    extern __shared__ char smraw[];
    uint32_t sA[NSTAGE], sB[NSTAGE];
    #pragma unroll
    for (int i = 0; i < NSTAGE; i++) {
        sA[i] = smem_u32(smraw) + i * TILE_B;
        sB[i] = smem_u32(smraw) + (NSTAGE + i) * TILE_B;
    }

    __shared__ float rowsum_s[BM];
    __shared__ float colsum_s[BN];

    const int tid  = threadIdx.x;
    const int wid  = tid >> 5;
    const int lane = tid & 31;
    const int wm = wid & 1;
    const int wn = wid >> 1;

    if (tid < BM) rowsum_s[tid] = 0.0f;
    if (tid < BN) colsum_s[tid] = 0.0f;

    const int rowbase = by * BM;
    const int colbase = bx * BN;
    const char* gA = (const char*)(g_zn + (size_t)rowbase * DDIM);
    const char* gB = (const char*)(g_zn + (size_t)colbase * DDIM);

    uint32_t acc[4][4][2];
    #pragma unroll
    for (int i = 0; i < 4; i++)
        #pragma unroll
        for (int j = 0; j < 4; j++) { acc[i][j][0] = 0u; acc[i][j][1] = 0u; }

    const int lrow = lane & 15;
    const int lseg = lane >> 4;

    load_chunk(sA[0], gA, 0, tid);
    load_chunk(sB[0], gB, 0, tid);
    CPCOMMIT();

    #pragma unroll 1
    for (int c = 0; c < NCHUNK; c++) {
        const int cur = c & 1;
        asm volatile("cp.async.wait_group 0;" ::: "memory");
        __syncthreads();
        if (c + 1 < NCHUNK) {
            load_chunk(sA[cur ^ 1], gA, c + 1, tid);
            load_chunk(sB[cur ^ 1], gB, c + 1, tid);
            CPCOMMIT();
        }

        #pragma unroll
        for (int kk = 0; kk < 4; kk++) {
            const int seg = 2 * kk + lseg;
            uint32_t a[4][4], b[2][4];
            #pragma unroll
            for (int mi = 0; mi < 4; mi++) {
                int r = wm * 64 + mi * 16 + lrow;
                uint32_t addr = sA[cur] + (uint32_t)(r * 128 + ((seg ^ (r & 7)) * 16));
                LDSM4(a[mi][0], a[mi][1], a[mi][2], a[mi][3], addr);
            }
            #pragma unroll
            for (int bt = 0; bt < 2; bt++) {
                int r = wn * 32 + bt * 16 + lrow;
                uint32_t addr = sB[cur] + (uint32_t)(r * 128 + ((seg ^ (r & 7)) * 16));
                LDSM4(b[bt][0], b[bt][1], b[bt][2], b[bt][3], addr);
            }
            #pragma unroll
            for (int mi = 0; mi < 4; mi++)
                #pragma unroll
                for (int bt = 0; bt < 2; bt++) {
                    MMAH(acc[mi][bt * 2 + 0], a[mi], b[bt][0], b[bt][2]);
                    MMAH(acc[mi][bt * 2 + 1], a[mi], b[bt][1], b[bt][3]);
                }
        }
    }

    // ---- epilogue ----
    const int qr = lane >> 2;
    const int qc = (lane & 3) * 2;
    float colp[4][2];
    #pragma unroll
    for (int nt = 0; nt < 4; nt++) { colp[nt][0] = 0.0f; colp[nt][1] = 0.0f; }

    #pragma unroll
    for (int mi = 0; mi < 4; mi++) {
        const int gi0 = rowbase + wm * 64 + mi * 16 + qr;
        const int gi1 = gi0 + 8;
        float rs0 = 0.0f, rs1 = 0.0f;
        #pragma unroll
        for (int nt = 0; nt < 4; nt++) {
            const int gj0 = colbase + wn * 32 + nt * 8 + qc;
            const int gj1 = gj0 + 1;
            const float2 lo = __half22float2(*(const __half2*)&acc[mi][nt][0]);
            const float2 hi = __half22float2(*(const __half2*)&acc[mi][nt][1]);
            const float d00 = lo.x, d01 = lo.y;
            const float d10 = hi.x, d11 = hi.y;

            float e00 = ex2_approx(fmaf(d00, EXP_SCALE, -EXP_SCALE));
            float e01 = ex2_approx(fmaf(d01, EXP_SCALE, -EXP_SCALE));
            float e10 = ex2_approx(fmaf(d10, EXP_SCALE, -EXP_SCALE));
            float e11 = ex2_approx(fmaf(d11, EXP_SCALE, -EXP_SCALE));
            if (gj0 <= gi0) e00 = 0.0f;
            if (gj1 <= gi0) e01 = 0.0f;
            if (gj0 <= gi1) e10 = 0.0f;
            if (gj1 <= gi1) e11 = 0.0f;

            if (gj0 == gi0 + NHALF) { float s = d00 * INV_T; g_pos[gi0] = s; g_pos[gj0] = s; }
            if (gj1 == gi0 + NHALF) { float s = d01 * INV_T; g_pos[gi0] = s; g_pos[gj1] = s; }
            if (gj0 == gi1 + NHALF) { float s = d10 * INV_T; g_pos[gi1] = s; g_pos[gj0] = s; }
            if (gj1 == gi1 + NHALF) { float s = d11 * INV_T; g_pos[gi1] = s; g_pos[gj1] = s; }

            rs0 += e00 + e01;
            rs1 += e10 + e11;
            colp[nt][0] += e00 + e10;
            colp[nt][1] += e01 + e11;
        }
        rs0 += __shfl_xor_sync(0xffffffffu, rs0, 1);
        rs0 += __shfl_xor_sync(0xffffffffu, rs0, 2);
        rs1 += __shfl_xor_sync(0xffffffffu, rs1, 1);
        rs1 += __shfl_xor_sync(0xffffffffu, rs1, 2);
        if ((lane & 3) == 0) {
            atomicAdd(&rowsum_s[wm * 64 + mi * 16 + qr], rs0);
            atomicAdd(&rowsum_s[wm * 64 + mi * 16 + qr + 8], rs1);
        }
    }
    #pragma unroll
    for (int nt = 0; nt < 4; nt++) {
        #pragma unroll
        for (int j = 0; j < 2; j++) {
            float v = colp[nt][j];
            v += __shfl_xor_sync(0xffffffffu, v, 4);
            v += __shfl_xor_sync(0xffffffffu, v, 8);
            v += __shfl_xor_sync(0xffffffffu, v, 16);
            if (lane < 4 && (lane & 3) == (qc >> 1))
                atomicAdd(&colsum_s[wn * 32 + nt * 8 + qc + j], v);
        }
    }
    __syncthreads();

    if (tid < BM) atomicAdd(&g_rowsum[rowbase + tid], rowsum_s[tid]);
    if (tid < BN) atomicAdd(&g_rowsum[colbase + tid], colsum_s[tid]);
}

// ---------------------------------------------------------------------------
// Kernel 3: loss mean, single 1024-thread block, vectorized + approx log
// ---------------------------------------------------------------------------
__global__ void k_final(float* __restrict__ out) {
    const int tid = threadIdx.x;    // 1024
    float sum = 0.0f;
    const float4* pos4 = (const float4*)g_pos;
    const float4* row4 = (const float4*)g_rowsum;
    #pragma unroll
    for (int i = 0; i < 2; i++) {
        const int idx = tid + i * 1024;      // 2048 float4 total
        float4 p = pos4[idx];
        float4 r = row4[idx];
        sum += -(p.x + p.y + p.z + p.w) + 4.0f * INV_T
             + (lg2_approx(r.x) + lg2_approx(r.y)
              + lg2_approx(r.z) + lg2_approx(r.w)) * LN2F;
    }
    #pragma unroll
    for (int off = 16; off > 0; off >>= 1)
        sum += __shfl_xor_sync(0xffffffffu, sum, off);
    __shared__ float red[32];
    if ((tid & 31) == 0) red[tid >> 5] = sum;
    __syncthreads();
    if (tid < 32) {
        float v = red[tid];
        #pragma unroll
        for (int off = 16; off > 0; off >>= 1)
            v += __shfl_xor_sync(0xffffffffu, v, off);
        if (tid == 0) out[0] = v / (float)TWO_N;
    }
}

extern "C" void kernel_launch(void* const* d_in, const int* in_sizes, int n_in,
                              void* d_out, int out_size) {
    const float* z1 = (const float*)d_in[0];
    const float* z2 = (const float*)d_in[1];
    float* out = (float*)d_out;

    static int attr_set = 0;
    if (!attr_set) {
        cudaFuncSetAttribute(k_sim, cudaFuncAttributeMaxDynamicSharedMemorySize,
                             SMEM_BYTES);
        attr_set = 1;
    }

    k_normalize<<<TWO_N / 8, 256>>>(z1, z2);   // 1 row/warp, grid 1024
    k_sim<<<NUPPER, 256, SMEM_BYTES>>>();
    k_final<<<1, 1024>>>(out);
}